// round 16
// baseline (speedup 1.0000x reference)
#include <cuda_runtime.h>
#include <cuda_bf16.h>
#include <math.h>
#include <stdint.h>

#define TT 2048      // B*S tokens
#define DD 1024      // model dim
#define FFD 4096     // ff dim
#define VV 32000     // vocab
#define HH 16        // heads
#define HD 64        // head dim
#define LL 6         // layers
#define SS 1024      // seq len
#define BB 2         // batch

// ---------------- weight scratch offsets (elements) ----------------
#define OFF_WQ   0ULL
#define OFF_WK   (OFF_WQ + 6ULL * 1024 * 1024)
#define OFF_WV   (OFF_WK + 6ULL * 1024 * 1024)
#define OFF_WO   (OFF_WV + 6ULL * 1024 * 1024)
#define OFF_W1   (OFF_WO + 6ULL * 1024 * 1024)
#define OFF_W2   (OFF_W1 + 6ULL * 1024 * 4096)
#define OFF_WOUT (OFF_W2 + 6ULL * 4096 * 1024)
#define W_TOTAL  (OFF_WOUT + 1024ULL * 32000)

// ---------------- scratch (no allocation allowed) ----------------
__device__ __nv_bfloat16 g_whi[W_TOTAL];
__device__ __nv_bfloat16 g_wlo[W_TOTAL];
__device__ float g_x[TT * DD];
__device__ __nv_bfloat16 g_qhi[TT * DD];
__device__ __nv_bfloat16 g_qlo[TT * DD];
__device__ __nv_bfloat16 g_khi[TT * DD];
__device__ __nv_bfloat16 g_klo[TT * DD];
__device__ __nv_bfloat16 g_vhi[TT * DD];
__device__ __nv_bfloat16 g_vlo[TT * DD];
__device__ __nv_bfloat16 g_hhi[TT * DD];
__device__ __nv_bfloat16 g_hlo[TT * DD];
__device__ __nv_bfloat16 g_athi[TT * DD];
__device__ __nv_bfloat16 g_atlo[TT * DD];
__device__ __nv_bfloat16 g_ffhi[TT * FFD];
__device__ __nv_bfloat16 g_fflo[TT * FFD];

// ---------------- baseline-PTX helpers ----------------
__device__ __forceinline__ uint32_t smem_u32(const void* p) {
    uint32_t a;
    asm("{ .reg .u64 t; cvta.to.shared.u64 t, %1; cvt.u32.u64 %0, t; }" : "=r"(a) : "l"(p));
    return a;
}
#define CP_ASYNC16(dst, src) \
    asm volatile("cp.async.cg.shared.global [%0], [%1], 16;" :: "r"(dst), "l"(src))
#define CP_COMMIT() asm volatile("cp.async.commit_group;" ::: "memory")
#define CP_WAIT0()  asm volatile("cp.async.wait_group 0;" ::: "memory")
#define LDSM4(r0, r1, r2, r3, a) \
    asm volatile("ldmatrix.sync.aligned.m8n8.x4.shared.b16 {%0,%1,%2,%3}, [%4];" \
                 : "=r"(r0), "=r"(r1), "=r"(r2), "=r"(r3) : "r"(a))
#define LDSM4T(r0, r1, r2, r3, a) \
    asm volatile("ldmatrix.sync.aligned.m8n8.x4.trans.shared.b16 {%0,%1,%2,%3}, [%4];" \
                 : "=r"(r0), "=r"(r1), "=r"(r2), "=r"(r3) : "r"(a))

__device__ __forceinline__ void mma_bf16(float* c, const uint32_t* a, const uint32_t* b) {
    asm volatile(
        "mma.sync.aligned.m16n8k16.row.col.f32.bf16.bf16.f32 "
        "{%0,%1,%2,%3}, {%4,%5,%6,%7}, {%8,%9}, {%0,%1,%2,%3};\n"
        : "+f"(c[0]), "+f"(c[1]), "+f"(c[2]), "+f"(c[3])
        : "r"(a[0]), "r"(a[1]), "r"(a[2]), "r"(a[3]), "r"(b[0]), "r"(b[1]));
}

__device__ __forceinline__ void fsplit(float v, __nv_bfloat16& h, __nv_bfloat16& l) {
    h = __float2bfloat16(v);
    l = __float2bfloat16(v - __bfloat162float(h));
}
// pack (f0 low, f1 high) into hi/lo bf16x2 words
__device__ __forceinline__ void split_bf16x2(float f0, float f1,
                                             uint32_t& hi, uint32_t& lo) {
    uint32_t h;
    asm("cvt.rn.bf16x2.f32 %0, %1, %2;" : "=r"(h) : "f"(f1), "f"(f0));
    float h0 = __uint_as_float(h << 16);
    float h1 = __uint_as_float(h & 0xffff0000u);
    float l0 = f0 - h0;
    float l1 = f1 - h1;
    uint32_t l;
    asm("cvt.rn.bf16x2.f32 %0, %1, %2;" : "=r"(l) : "f"(l1), "f"(l0));
    hi = h; lo = l;
}

// ---------------- weight transpose+split: [K,N] fp32 -> [N,K] bf16 hi/lo ----------------
__global__ __launch_bounds__(256) void tsplit_kernel(const float* __restrict__ src,
                                                     __nv_bfloat16* __restrict__ dhi,
                                                     __nv_bfloat16* __restrict__ dlo,
                                                     int K, int N) {
    __shared__ float s[32][33];
    size_t zo = (size_t)blockIdx.z * K * N;
    src += zo; dhi += zo; dlo += zo;
    int n0 = blockIdx.x * 32, k0 = blockIdx.y * 32;
    int tx = threadIdx.x & 31, ty = threadIdx.x >> 5;
#pragma unroll
    for (int i = 0; i < 4; i++)
        s[ty + 8 * i][tx] = src[(size_t)(k0 + ty + 8 * i) * N + n0 + tx];
    __syncthreads();
#pragma unroll
    for (int i = 0; i < 4; i++) {
        int n = n0 + ty + 8 * i, k = k0 + tx;
        float v = s[tx][ty + 8 * i];
        __nv_bfloat16 h, l;
        fsplit(v, h, l);
        dhi[(size_t)n * K + k] = h;
        dlo[(size_t)n * K + k] = l;
    }
}

// ---------------- embedding + positional encoding ----------------
__global__ void embed_kernel(const float* __restrict__ emb,
                             const int* __restrict__ ids,
                             float* __restrict__ x) {
    int idx = blockIdx.x * 256 + threadIdx.x;
    if (idx >= TT * DD) return;
    int t = idx >> 10;
    int d = idx & (DD - 1);
    int pos = t & (SS - 1);
    float val = emb[ids[t] * DD + d] * 32.0f;
    float ang = (float)pos * expf((float)(d & ~1) * (-9.210340371976184f / 1024.0f));
    val += (d & 1) ? cosf(ang) : sinf(ang);
    x[idx] = val;
}

// ---------------- layernorm -> split bf16 output ----------------
__global__ __launch_bounds__(256) void ln_kernel(const float* __restrict__ x,
                                                 const float* __restrict__ g,
                                                 const float* __restrict__ bta,
                                                 __nv_bfloat16* __restrict__ ohi,
                                                 __nv_bfloat16* __restrict__ olo) {
    int row = blockIdx.x;
    const float* xr = x + (size_t)row * DD;
    float s1 = 0.f, s2 = 0.f;
    for (int i = threadIdx.x; i < DD; i += 256) {
        float v = xr[i];
        s1 += v;
        s2 = fmaf(v, v, s2);
    }
    for (int o = 16; o; o >>= 1) {
        s1 += __shfl_xor_sync(0xffffffffu, s1, o);
        s2 += __shfl_xor_sync(0xffffffffu, s2, o);
    }
    __shared__ float r1[8], r2[8];
    __shared__ float smean, srstd;
    int w = threadIdx.x >> 5, lane = threadIdx.x & 31;
    if (lane == 0) { r1[w] = s1; r2[w] = s2; }
    __syncthreads();
    if (threadIdx.x == 0) {
        float t1 = 0.f, t2 = 0.f;
        for (int i = 0; i < 8; i++) { t1 += r1[i]; t2 += r2[i]; }
        float mean = t1 * (1.0f / DD);
        float var  = t2 * (1.0f / DD) - mean * mean;
        smean = mean;
        srstd = rsqrtf(var + 1e-5f);
    }
    __syncthreads();
    float mean = smean, rstd = srstd;
    for (int i = threadIdx.x; i < DD; i += 256) {
        float v = (xr[i] - mean) * rstd * g[i] + bta[i];
        __nv_bfloat16 h, l;
        fsplit(v, h, l);
        ohi[(size_t)row * DD + i] = h;
        olo[(size_t)row * DD + i] = l;
    }
}

// ---------------- bf16x3 mma.sync GEMM, templated on tile height ----------------
// MF = m-fragments per warp (BM = 32*MF). Warps: 2(m) x 4(n). BN = 128, BK = 32.
#define TST 80
#define TILE_BROWS (128 * TST)
#define GEMM_SMEM128 (2 * (2 * 128 * TST + 2 * 128 * TST))   // 81920
#define GEMM_SMEM64  (2 * (2 * 64 * TST + 2 * 128 * TST))    // 61440

template <int MF>
__device__ __forceinline__ void gemm_body_t(
    const __nv_bfloat16* __restrict__ Ahg, const __nv_bfloat16* __restrict__ Alg,
    const __nv_bfloat16* __restrict__ Bhg, const __nv_bfloat16* __restrict__ Blg,
    const float* __restrict__ bias, const float* __restrict__ res,
    float* __restrict__ Cf, __nv_bfloat16* __restrict__ Chi, __nv_bfloat16* __restrict__ Clo,
    int N, int K, int act, int bm, int bn, char* smem)
{
    constexpr int BM = MF * 32;
    constexpr int TILE_A = BM * TST;
    constexpr int BUF = 2 * TILE_A + 2 * TILE_BROWS;

    uint32_t sbase = smem_u32(smem);
    int t = threadIdx.x, w = t >> 5, l = t & 31;
    int wm = w >> 2, wn = w & 3;
    int m_base = wm * (MF * 16), n_base = wn * 32;

    int lrow = w * 8 + (l & 7);
    int lc = l >> 3;

    float acc[MF][4][4];
#pragma unroll
    for (int mf = 0; mf < MF; mf++)
#pragma unroll
        for (int nf = 0; nf < 4; nf++)
#pragma unroll
            for (int r = 0; r < 4; r++) acc[mf][nf][r] = 0.f;

    int S = K >> 5;

    auto load_stage = [&](int s, int bsel) {
        int k0 = s << 5;
        uint32_t bufb = sbase + bsel * BUF;
        // A tiles (BM rows)
#pragma unroll
        for (int half = 0; half < 2; half++) {
            const __nv_bfloat16* src = half ? Alg : Ahg;
            uint32_t tb = bufb + half * TILE_A;
#pragma unroll
            for (int i = 0; i < BM / 64; i++) {
                int row = lrow + i * 64;
                const void* gp = src + (size_t)(bm * BM + row) * K + k0 + lc * 8;
                CP_ASYNC16(tb + row * TST + lc * 16, gp);
            }
        }
        // B tiles (128 rows)
#pragma unroll
        for (int half = 0; half < 2; half++) {
            const __nv_bfloat16* src = half ? Blg : Bhg;
            uint32_t tb = bufb + 2 * TILE_A + half * TILE_BROWS;
#pragma unroll
            for (int i = 0; i < 2; i++) {
                int row = lrow + i * 64;
                const void* gp = src + (size_t)((bn << 7) + row) * K + k0 + lc * 8;
                CP_ASYNC16(tb + row * TST + lc * 16, gp);
            }
        }
    };

    load_stage(0, 0);
    CP_COMMIT();

    for (int s = 0; s < S; s++) {
        int b = s & 1;
        CP_WAIT0();
        __syncthreads();
        if (s + 1 < S) { load_stage(s + 1, b ^ 1); CP_COMMIT(); }

        uint32_t bufb = sbase + b * BUF;
        uint32_t aHb = bufb, aLb = bufb + TILE_A;
        uint32_t bHb = bufb + 2 * TILE_A, bLb = bHb + TILE_BROWS;
#pragma unroll
        for (int ks = 0; ks < 2; ks++) {
            int cb = ks * 2;
            uint32_t bh[4][2], bl[4][2];
#pragma unroll
            for (int nfp = 0; nfp < 2; nfp++) {
                int nr = n_base + nfp * 16 + ((l >> 4) << 3) + (l & 7);
                int cc = cb + ((l >> 3) & 1);
                uint32_t addr = (uint32_t)(nr * TST + cc * 16);
                uint32_t r0, r1, r2, r3;
                LDSM4(r0, r1, r2, r3, bHb + addr);
                bh[nfp * 2][0] = r0; bh[nfp * 2][1] = r1;
                bh[nfp * 2 + 1][0] = r2; bh[nfp * 2 + 1][1] = r3;
                LDSM4(r0, r1, r2, r3, bLb + addr);
                bl[nfp * 2][0] = r0; bl[nfp * 2][1] = r1;
                bl[nfp * 2 + 1][0] = r2; bl[nfp * 2 + 1][1] = r3;
            }
#pragma unroll
            for (int mf = 0; mf < MF; mf++) {
                int mr = m_base + mf * 16 + (l & 15);
                int cc = cb + (l >> 4);
                uint32_t addr = (uint32_t)(mr * TST + cc * 16);
                uint32_t ah[4], al[4];
                LDSM4(ah[0], ah[1], ah[2], ah[3], aHb + addr);
                LDSM4(al[0], al[1], al[2], al[3], aLb + addr);
#pragma unroll
                for (int nf = 0; nf < 4; nf++) mma_bf16(acc[mf][nf], ah, bh[nf]);
#pragma unroll
                for (int nf = 0; nf < 4; nf++) mma_bf16(acc[mf][nf], ah, bl[nf]);
#pragma unroll
                for (int nf = 0; nf < 4; nf++) mma_bf16(acc[mf][nf], al, bh[nf]);
            }
        }
    }

    int gid = l >> 2, tig = l & 3;
#pragma unroll
    for (int mf = 0; mf < MF; mf++) {
        int row0 = bm * BM + m_base + mf * 16 + gid;
#pragma unroll
        for (int nf = 0; nf < 4; nf++) {
            int col = (bn << 7) + n_base + nf * 8 + tig * 2;
            float bx = 0.f, by = 0.f;
            if (bias) { bx = bias[col]; by = bias[col + 1]; }
#pragma unroll
            for (int half = 0; half < 2; half++) {
                int row = row0 + half * 8;
                float vx = acc[mf][nf][half * 2 + 0] + bx;
                float vy = acc[mf][nf][half * 2 + 1] + by;
                size_t o = (size_t)row * N + col;
                if (Chi) {
                    if (act) {
                        vx = 0.5f * vx * (1.0f + erff(vx * 0.70710678118654752f));
                        vy = 0.5f * vy * (1.0f + erff(vy * 0.70710678118654752f));
                    }
                    uint32_t ph, pl;
                    split_bf16x2(vx, vy, ph, pl);
                    *(uint32_t*)(Chi + o) = ph;
                    *(uint32_t*)(Clo + o) = pl;
                } else {
                    if (res) {
                        float2 rr = *(const float2*)(res + o);
                        vx += rr.x; vy += rr.y;
                    }
                    float2 ov; ov.x = vx; ov.y = vy;
                    *(float2*)(Cf + o) = ov;
                }
            }
        }
    }
}

// 128x128 tiles (FF1, logits)
__global__ __launch_bounds__(256, 2) void gemm128_kernel(
    const __nv_bfloat16* ah, const __nv_bfloat16* al,
    const __nv_bfloat16* bh, const __nv_bfloat16* bl,
    const float* bias, const float* res,
    float* Cf, __nv_bfloat16* Chi, __nv_bfloat16* Clo, int N, int K, int act, int swap) {
    extern __shared__ char smem[];
    int bm = swap ? blockIdx.x : blockIdx.y;
    int bn = swap ? blockIdx.y : blockIdx.x;
    gemm_body_t<4>(ah, al, bh, bl, bias, res, Cf, Chi, Clo, N, K, act, bm, bn, smem);
}

// 64x128 tiles (Wo-proj, W2-proj: 256-CTA grids for full SM fill)
__global__ __launch_bounds__(256, 2) void gemm64_kernel(
    const __nv_bfloat16* ah, const __nv_bfloat16* al,
    const __nv_bfloat16* bh, const __nv_bfloat16* bl,
    const float* bias, const float* res,
    float* Cf, __nv_bfloat16* Chi, __nv_bfloat16* Clo, int N, int K, int act) {
    extern __shared__ char smem[];
    gemm_body_t<2>(ah, al, bh, bl, bias, res, Cf, Chi, Clo, N, K, act,
                   blockIdx.y, blockIdx.x, smem);
}

// 64x128 QKV (768-CTA grid)
__global__ __launch_bounds__(256, 2) void gemm64_qkv_kernel(
    const __nv_bfloat16* ah, const __nv_bfloat16* al,
    const __nv_bfloat16* wqh, const __nv_bfloat16* wql,
    const __nv_bfloat16* wkh, const __nv_bfloat16* wkl,
    const __nv_bfloat16* wvh, const __nv_bfloat16* wvl,
    const float* bq, const float* bk, const float* bv,
    __nv_bfloat16* qh, __nv_bfloat16* ql,
    __nv_bfloat16* kh, __nv_bfloat16* kl,
    __nv_bfloat16* vh, __nv_bfloat16* vl) {
    extern __shared__ char smem[];
    const __nv_bfloat16 *bhp, *blp; const float* bi;
    __nv_bfloat16 *oh, *ol;
    if (blockIdx.z == 0)      { bhp = wqh; blp = wql; bi = bq; oh = qh; ol = ql; }
    else if (blockIdx.z == 1) { bhp = wkh; blp = wkl; bi = bk; oh = kh; ol = kl; }
    else                      { bhp = wvh; blp = wvl; bi = bv; oh = vh; ol = vl; }
    gemm_body_t<2>(ah, al, bhp, blp, bi, nullptr, nullptr, oh, ol, DD, DD, 0,
                   blockIdx.y, blockIdx.x, smem);
}

// ---------------- tensor-core flash attention (bf16x3) ----------------
// CTA: 64 q rows x (h, b); 128 threads = 4 warps x m16 slice; kt tiles of 64 keys.
// Row = 64 dims x 2B = 128B; stride 144B (=4-bank step, 8-row phases conflict-free).
#define AST 144
#define ATILE (64 * AST)        // 9216 B
#define ATT_SMEM (6 * ATILE)    // Qh,Ql,Kh,Kl,Vh,Vl = 55296

__global__ __launch_bounds__(128) void flash_attn_kernel(
    const __nv_bfloat16* __restrict__ qhi, const __nv_bfloat16* __restrict__ qlo,
    const __nv_bfloat16* __restrict__ khi, const __nv_bfloat16* __restrict__ klo,
    const __nv_bfloat16* __restrict__ vhi, const __nv_bfloat16* __restrict__ vlo,
    __nv_bfloat16* __restrict__ Ohi, __nv_bfloat16* __restrict__ Olo)
{
    extern __shared__ char sm[];
    uint32_t sb = smem_u32(sm);
    uint32_t Qh = sb, Ql = sb + ATILE, Kh = sb + 2 * ATILE, Kl = sb + 3 * ATILE;
    uint32_t Vh = sb + 4 * ATILE, Vl = sb + 5 * ATILE;

    int t = threadIdx.x, wid = t >> 5, l = t & 31;
    int gid = l >> 2, tig = l & 3;
    int bqx = blockIdx.x, h = blockIdx.y, b = blockIdx.z;
    int q0 = bqx * 64;
    int m_base = wid * 16;
    size_t tok0 = (size_t)(b * SS) * DD + h * 64;   // +token*DD to index

    // ---- load Q tile (hi/lo) ----
    {
        int chunk = t & 7, row0 = t >> 3;           // 16 rows per pass
#pragma unroll
        for (int i = 0; i < 4; i++) {
            int row = row0 + 16 * i;
            size_t g = tok0 + (size_t)(q0 + row) * DD + chunk * 8;
            CP_ASYNC16(Qh + row * AST + chunk * 16, qhi + g);
            CP_ASYNC16(Ql + row * AST + chunk * 16, qlo + g);
        }
    }
    CP_COMMIT();

    float o[8][4];
#pragma unroll
    for (int nf = 0; nf < 8; nf++)
#pragma unroll
        for (int r = 0; r < 4; r++) o[nf][r] = 0.f;
    float m0 = -1e30f, m1 = -1e30f, l0 = 0.f, l1 = 0.f;

    int ntiles = bqx + 1;
    for (int kt = 0; kt < ntiles; kt++) {
        // ---- load K/V tile (hi/lo) ----
        {
            int chunk = t & 7, row0 = t >> 3;
#pragma unroll
            for (int i = 0; i < 4; i++) {
                int row = row0 + 16 * i;
                size_t g = tok0 + (size_t)(kt * 64 + row) * DD + chunk * 8;
                CP_ASYNC16(Kh + row * AST + chunk * 16, khi + g);
                CP_ASYNC16(Kl + row * AST + chunk * 16, klo + g);
                CP_ASYNC16(Vh + row * AST + chunk * 16, vhi + g);
                CP_ASYNC16(Vl + row * AST + chunk * 16, vlo + g);
            }
        }
        CP_COMMIT();
        CP_WAIT0();
        __syncthreads();

        // ---- S = Q K^T (3-pass bf16x3) ----
        float sacc[8][4];
#pragma unroll
        for (int nf = 0; nf < 8; nf++)
#pragma unroll
            for (int r = 0; r < 4; r++) sacc[nf][r] = 0.f;
#pragma unroll
        for (int kb = 0; kb < 4; kb++) {
            uint32_t aoff = (uint32_t)((m_base + (l & 15)) * AST + (kb * 2 + (l >> 4)) * 16);
            uint32_t qh4[4], ql4[4];
            LDSM4(qh4[0], qh4[1], qh4[2], qh4[3], Qh + aoff);
            LDSM4(ql4[0], ql4[1], ql4[2], ql4[3], Ql + aoff);
#pragma unroll
            for (int ng = 0; ng < 4; ng++) {
                uint32_t boff = (uint32_t)((ng * 16 + ((l >> 4) << 3) + (l & 7)) * AST
                                           + (kb * 2 + ((l >> 3) & 1)) * 16);
                uint32_t kh4[4], kl4[4];
                LDSM4(kh4[0], kh4[1], kh4[2], kh4[3], Kh + boff);
                LDSM4(kl4[0], kl4[1], kl4[2], kl4[3], Kl + boff);
                mma_bf16(sacc[2 * ng],     qh4, kh4);
                mma_bf16(sacc[2 * ng + 1], qh4, kh4 + 2);
                mma_bf16(sacc[2 * ng],     qh4, kl4);
                mma_bf16(sacc[2 * ng + 1], qh4, kl4 + 2);
                mma_bf16(sacc[2 * ng],     ql4, kh4);
                mma_bf16(sacc[2 * ng + 1], ql4, kh4 + 2);
            }
        }

        // ---- scale + causal mask ----
#pragma unroll
        for (int nf = 0; nf < 8; nf++)
#pragma unroll
            for (int r = 0; r < 4; r++) sacc[nf][r] *= 0.125f;
        if (kt == bqx) {
            int grow0 = q0 + m_base + gid, grow1 = grow0 + 8;
#pragma unroll
            for (int nf = 0; nf < 8; nf++) {
                int gc = kt * 64 + nf * 8 + tig * 2;
                if (gc > grow0)     sacc[nf][0] = -1e30f;
                if (gc + 1 > grow0) sacc[nf][1] = -1e30f;
                if (gc > grow1)     sacc[nf][2] = -1e30f;
                if (gc + 1 > grow1) sacc[nf][3] = -1e30f;
            }
        }

        // ---- online softmax (registers + shfl over 4 lanes/row) ----
        float mx0 = -1e30f, mx1 = -1e30f;
#pragma unroll
        for (int nf = 0; nf < 8; nf++) {
            mx0 = fmaxf(mx0, fmaxf(sacc[nf][0], sacc[nf][1]));
            mx1 = fmaxf(mx1, fmaxf(sacc[nf][2], sacc[nf][3]));
        }
        mx0 = fmaxf(mx0, __shfl_xor_sync(0xffffffffu, mx0, 1));
        mx0 = fmaxf(mx0, __shfl_xor_sync(0xffffffffu, mx0, 2));
        mx1 = fmaxf(mx1, __shfl_xor_sync(0xffffffffu, mx1, 1));
        mx1 = fmaxf(mx1, __shfl_xor_sync(0xffffffffu, mx1, 2));
        float mn0 = fmaxf(m0, mx0), mn1 = fmaxf(m1, mx1);
        float f0 = __expf(m0 - mn0), f1 = __expf(m1 - mn1);
        float s0 = 0.f, s1 = 0.f;
#pragma unroll
        for (int nf = 0; nf < 8; nf++) {
            float p0 = __expf(sacc[nf][0] - mn0);
            float p1 = __expf(sacc[nf][1] - mn0);
            float p2 = __expf(sacc[nf][2] - mn1);
            float p3 = __expf(sacc[nf][3] - mn1);
            sacc[nf][0] = p0; sacc[nf][1] = p1; sacc[nf][2] = p2; sacc[nf][3] = p3;
            s0 += p0 + p1; s1 += p2 + p3;
        }
        s0 += __shfl_xor_sync(0xffffffffu, s0, 1);
        s0 += __shfl_xor_sync(0xffffffffu, s0, 2);
        s1 += __shfl_xor_sync(0xffffffffu, s1, 1);
        s1 += __shfl_xor_sync(0xffffffffu, s1, 2);
        l0 = l0 * f0 + s0; l1 = l1 * f1 + s1;
        m0 = mn0; m1 = mn1;
#pragma unroll
        for (int nf = 0; nf < 8; nf++) {
            o[nf][0] *= f0; o[nf][1] *= f0; o[nf][2] *= f1; o[nf][3] *= f1;
        }

        // ---- P -> A fragments (C(m16n16) == A(m16k16) identity), split hi/lo ----
        uint32_t phi[4][4], plo[4][4];
#pragma unroll
        for (int kb = 0; kb < 4; kb++) {
            split_bf16x2(sacc[2 * kb][0],     sacc[2 * kb][1],     phi[kb][0], plo[kb][0]);
            split_bf16x2(sacc[2 * kb][2],     sacc[2 * kb][3],     phi[kb][1], plo[kb][1]);
            split_bf16x2(sacc[2 * kb + 1][0], sacc[2 * kb + 1][1], phi[kb][2], plo[kb][2]);
            split_bf16x2(sacc[2 * kb + 1][2], sacc[2 * kb + 1][3], phi[kb][3], plo[kb][3]);
        }

        // ---- O += P V (V via ldmatrix.trans, 3-pass) ----
#pragma unroll
        for (int kb = 0; kb < 4; kb++) {
#pragma unroll
            for (int dg = 0; dg < 4; dg++) {
                uint32_t voff = (uint32_t)((kb * 16 + ((l >> 3) & 1) * 8 + (l & 7)) * AST
                                           + dg * 32 + (l >> 4) * 16);
                uint32_t vh4[4], vl4[4];
                LDSM4T(vh4[0], vh4[1], vh4[2], vh4[3], Vh + voff);
                LDSM4T(vl4[0], vl4[1], vl4[2], vl4[3], Vl + voff);
                mma_bf16(o[2 * dg],     phi[kb], vh4);
                mma_bf16(o[2 * dg + 1], phi[kb], vh4 + 2);
                mma_bf16(o[2 * dg],     phi[kb], vl4);
                mma_bf16(o[2 * dg + 1], phi[kb], vl4 + 2);
                mma_bf16(o[2 * dg],     plo[kb], vh4);
                mma_bf16(o[2 * dg + 1], plo[kb], vh4 + 2);
            }
        }
        __syncthreads();
    }

    // ---- normalize + split-store ----
    float inv0 = 1.0f / l0, inv1 = 1.0f / l1;
    int row0 = b * SS + q0 + m_base + gid;
#pragma unroll
    for (int nf = 0; nf < 8; nf++) {
        int col = h * 64 + nf * 8 + tig * 2;
        uint32_t ph, pl;
        split_bf16x2(o[nf][0] * inv0, o[nf][1] * inv0, ph, pl);
        size_t oa = (size_t)row0 * DD + col;
        *(uint32_t*)(Ohi + oa) = ph;
        *(uint32_t*)(Olo + oa) = pl;
        split_bf16x2(o[nf][2] * inv1, o[nf][3] * inv1, ph, pl);
        size_t ob = (size_t)(row0 + 8) * DD + col;
        *(uint32_t*)(Ohi + ob) = ph;
        *(uint32_t*)(Olo + ob) = pl;
    }
}

// ---------------- launch ----------------
extern "C" void kernel_launch(void* const* d_in, const int* in_sizes, int n_in,
                              void* d_out, int out_size) {
    const float* emb  = (const float*)d_in[0];
    const float* Wq   = (const float*)d_in[1];
    const float* bq   = (const float*)d_in[2];
    const float* Wk   = (const float*)d_in[3];
    const float* bk   = (const float*)d_in[4];
    const float* Wv   = (const float*)d_in[5];
    const float* bv   = (const float*)d_in[6];
    const float* Wo   = (const float*)d_in[7];
    const float* bo   = (const float*)d_in[8];
    const float* ln1g = (const float*)d_in[9];
    const float* ln1b = (const float*)d_in[10];
    const float* W1   = (const float*)d_in[11];
    const float* b1   = (const float*)d_in[12];
    const float* W2   = (const float*)d_in[13];
    const float* b2   = (const float*)d_in[14];
    const float* ln2g = (const float*)d_in[15];
    const float* ln2b = (const float*)d_in[16];
    const float* lnfg = (const float*)d_in[17];
    const float* lnfb = (const float*)d_in[18];
    const float* Wout = (const float*)d_in[19];
    const int*   ids  = (const int*)d_in[20];

    __nv_bfloat16 *whi, *wlo, *hhi, *hlo, *athi, *atlo, *ffhi, *fflo;
    __nv_bfloat16 *qhi, *qlo, *khi, *klo, *vhi, *vlo;
    float *x;
    cudaGetSymbolAddress((void**)&whi, g_whi);
    cudaGetSymbolAddress((void**)&wlo, g_wlo);
    cudaGetSymbolAddress((void**)&x,   g_x);
    cudaGetSymbolAddress((void**)&qhi, g_qhi);
    cudaGetSymbolAddress((void**)&qlo, g_qlo);
    cudaGetSymbolAddress((void**)&khi, g_khi);
    cudaGetSymbolAddress((void**)&klo, g_klo);
    cudaGetSymbolAddress((void**)&vhi, g_vhi);
    cudaGetSymbolAddress((void**)&vlo, g_vlo);
    cudaGetSymbolAddress((void**)&hhi, g_hhi);
    cudaGetSymbolAddress((void**)&hlo, g_hlo);
    cudaGetSymbolAddress((void**)&athi, g_athi);
    cudaGetSymbolAddress((void**)&atlo, g_atlo);
    cudaGetSymbolAddress((void**)&ffhi, g_ffhi);
    cudaGetSymbolAddress((void**)&fflo, g_fflo);

    static int attr_set = 0;
    if (!attr_set) {
        cudaFuncSetAttribute(flash_attn_kernel, cudaFuncAttributeMaxDynamicSharedMemorySize, ATT_SMEM);
        cudaFuncSetAttribute(gemm128_kernel, cudaFuncAttributeMaxDynamicSharedMemorySize, GEMM_SMEM128);
        cudaFuncSetAttribute(gemm64_kernel, cudaFuncAttributeMaxDynamicSharedMemorySize, GEMM_SMEM64);
        cudaFuncSetAttribute(gemm64_qkv_kernel, cudaFuncAttributeMaxDynamicSharedMemorySize, GEMM_SMEM64);
        attr_set = 1;
    }

    // ---- weight prep: transpose + split ----
    tsplit_kernel<<<dim3(DD / 32, DD / 32, LL), 256>>>(Wq, whi + OFF_WQ, wlo + OFF_WQ, DD, DD);
    tsplit_kernel<<<dim3(DD / 32, DD / 32, LL), 256>>>(Wk, whi + OFF_WK, wlo + OFF_WK, DD, DD);
    tsplit_kernel<<<dim3(DD / 32, DD / 32, LL), 256>>>(Wv, whi + OFF_WV, wlo + OFF_WV, DD, DD);
    tsplit_kernel<<<dim3(DD / 32, DD / 32, LL), 256>>>(Wo, whi + OFF_WO, wlo + OFF_WO, DD, DD);
    tsplit_kernel<<<dim3(FFD / 32, DD / 32, LL), 256>>>(W1, whi + OFF_W1, wlo + OFF_W1, DD, FFD);
    tsplit_kernel<<<dim3(DD / 32, FFD / 32, LL), 256>>>(W2, whi + OFF_W2, wlo + OFF_W2, FFD, DD);
    tsplit_kernel<<<dim3(VV / 32, DD / 32, 1), 256>>>(Wout, whi + OFF_WOUT, wlo + OFF_WOUT, DD, VV);

    embed_kernel<<<(TT * DD) / 256, 256>>>(emb, ids, x);

    dim3 gN64(DD / 128, TT / 64);        // (8, 32)  = 256 CTAs
    dim3 gQKV(DD / 128, TT / 64, 3);     // (8, 32, 3) = 768 CTAs
    dim3 gFF1(FFD / 128, TT / 128);      // (32, 16) = 512 CTAs
    dim3 gOut(TT / 128, VV / 128);       // (16, 250)
    dim3 gAttn(SS / 64, HH, BB);         // (16, 16, 2)

    for (int l = 0; l < LL; l++) {
        size_t wo1 = (size_t)l * DD * DD;
        size_t woF = (size_t)l * DD * FFD;
        ln_kernel<<<TT, 256>>>(x, ln1g + l * DD, ln1b + l * DD, hhi, hlo);
        gemm64_qkv_kernel<<<gQKV, 256, GEMM_SMEM64>>>(
            hhi, hlo,
            whi + OFF_WQ + wo1, wlo + OFF_WQ + wo1,
            whi + OFF_WK + wo1, wlo + OFF_WK + wo1,
            whi + OFF_WV + wo1, wlo + OFF_WV + wo1,
            bq + l * DD, bk + l * DD, bv + l * DD,
            qhi, qlo, khi, klo, vhi, vlo);
        flash_attn_kernel<<<gAttn, 128, ATT_SMEM>>>(qhi, qlo, khi, klo, vhi, vlo, athi, atlo);
        gemm64_kernel<<<gN64, 256, GEMM_SMEM64>>>(
            athi, atlo, whi + OFF_WO + wo1, wlo + OFF_WO + wo1,
            bo + l * DD, x, x, nullptr, nullptr, DD, DD, 0);
        ln_kernel<<<TT, 256>>>(x, ln2g + l * DD, ln2b + l * DD, hhi, hlo);
        gemm128_kernel<<<gFF1, 256, GEMM_SMEM128>>>(
            hhi, hlo, whi + OFF_W1 + woF, wlo + OFF_W1 + woF,
            b1 + l * FFD, nullptr, nullptr, ffhi, fflo, FFD, DD, 1, 0);
        gemm64_kernel<<<gN64, 256, GEMM_SMEM64>>>(
            ffhi, fflo, whi + OFF_W2 + woF, wlo + OFF_W2 + woF,
            b2 + l * DD, x, x, nullptr, nullptr, DD, FFD, 0);
    }
    ln_kernel<<<TT, 256>>>(x, lnfg, lnfb, hhi, hlo);
    gemm128_kernel<<<gOut, 256, GEMM_SMEM128>>>(
        hhi, hlo, whi + OFF_WOUT, wlo + OFF_WOUT,
        nullptr, nullptr, (float*)d_out, nullptr, nullptr, VV, DD, 0, 1);
}

// round 17
// speedup vs baseline: 1.0726x; 1.0726x over previous
#include <cuda_runtime.h>
#include <cuda_bf16.h>
#include <math.h>
#include <stdint.h>

#define TT 2048      // B*S tokens
#define DD 1024      // model dim
#define FFD 4096     // ff dim
#define VV 32000     // vocab
#define HH 16        // heads
#define HD 64        // head dim
#define LL 6         // layers
#define SS 1024      // seq len
#define BB 2         // batch

// ---------------- weight scratch offsets (elements) ----------------
#define OFF_WQ   0ULL
#define OFF_WK   (OFF_WQ + 6ULL * 1024 * 1024)
#define OFF_WV   (OFF_WK + 6ULL * 1024 * 1024)
#define OFF_WO   (OFF_WV + 6ULL * 1024 * 1024)
#define OFF_W1   (OFF_WO + 6ULL * 1024 * 1024)
#define OFF_W2   (OFF_W1 + 6ULL * 1024 * 4096)
#define OFF_WOUT (OFF_W2 + 6ULL * 4096 * 1024)
#define W_TOTAL  (OFF_WOUT + 1024ULL * 32000)

// ---------------- scratch (no allocation allowed) ----------------
__device__ __nv_bfloat16 g_whi[W_TOTAL];
__device__ __nv_bfloat16 g_wlo[W_TOTAL];
__device__ float g_x[TT * DD];
__device__ float g_p0[TT * DD];
__device__ float g_p1[TT * DD];
__device__ __nv_bfloat16 g_qhi[TT * DD];
__device__ __nv_bfloat16 g_qlo[TT * DD];
__device__ __nv_bfloat16 g_khi[TT * DD];
__device__ __nv_bfloat16 g_klo[TT * DD];
__device__ __nv_bfloat16 g_vhi[TT * DD];
__device__ __nv_bfloat16 g_vlo[TT * DD];
__device__ __nv_bfloat16 g_hhi[TT * DD];
__device__ __nv_bfloat16 g_hlo[TT * DD];
__device__ __nv_bfloat16 g_athi[TT * DD];
__device__ __nv_bfloat16 g_atlo[TT * DD];
__device__ __nv_bfloat16 g_ffhi[TT * FFD];
__device__ __nv_bfloat16 g_fflo[TT * FFD];

// ---------------- baseline-PTX helpers ----------------
__device__ __forceinline__ uint32_t smem_u32(const void* p) {
    uint32_t a;
    asm("{ .reg .u64 t; cvta.to.shared.u64 t, %1; cvt.u32.u64 %0, t; }" : "=r"(a) : "l"(p));
    return a;
}
#define CP_ASYNC16(dst, src) \
    asm volatile("cp.async.cg.shared.global [%0], [%1], 16;" :: "r"(dst), "l"(src))
#define CP_COMMIT() asm volatile("cp.async.commit_group;" ::: "memory")
#define CP_WAIT0()  asm volatile("cp.async.wait_group 0;" ::: "memory")
#define LDSM4(r0, r1, r2, r3, a) \
    asm volatile("ldmatrix.sync.aligned.m8n8.x4.shared.b16 {%0,%1,%2,%3}, [%4];" \
                 : "=r"(r0), "=r"(r1), "=r"(r2), "=r"(r3) : "r"(a))
#define LDSM4T(r0, r1, r2, r3, a) \
    asm volatile("ldmatrix.sync.aligned.m8n8.x4.trans.shared.b16 {%0,%1,%2,%3}, [%4];" \
                 : "=r"(r0), "=r"(r1), "=r"(r2), "=r"(r3) : "r"(a))

__device__ __forceinline__ void mma_bf16(float* c, const uint32_t* a, const uint32_t* b) {
    asm volatile(
        "mma.sync.aligned.m16n8k16.row.col.f32.bf16.bf16.f32 "
        "{%0,%1,%2,%3}, {%4,%5,%6,%7}, {%8,%9}, {%0,%1,%2,%3};\n"
        : "+f"(c[0]), "+f"(c[1]), "+f"(c[2]), "+f"(c[3])
        : "r"(a[0]), "r"(a[1]), "r"(a[2]), "r"(a[3]), "r"(b[0]), "r"(b[1]));
}

__device__ __forceinline__ void fsplit(float v, __nv_bfloat16& h, __nv_bfloat16& l) {
    h = __float2bfloat16(v);
    l = __float2bfloat16(v - __bfloat162float(h));
}
// pack (f0 low, f1 high) into hi/lo bf16x2 words
__device__ __forceinline__ void split_bf16x2(float f0, float f1,
                                             uint32_t& hi, uint32_t& lo) {
    uint32_t h;
    asm("cvt.rn.bf16x2.f32 %0, %1, %2;" : "=r"(h) : "f"(f1), "f"(f0));
    float h0 = __uint_as_float(h << 16);
    float h1 = __uint_as_float(h & 0xffff0000u);
    float l0 = f0 - h0;
    float l1 = f1 - h1;
    uint32_t l;
    asm("cvt.rn.bf16x2.f32 %0, %1, %2;" : "=r"(l) : "f"(l1), "f"(l0));
    hi = h; lo = l;
}

// ---------------- weight transpose+split: [K,N] fp32 -> [N,K] bf16 hi/lo ----------------
__global__ __launch_bounds__(256) void tsplit_kernel(const float* __restrict__ src,
                                                     __nv_bfloat16* __restrict__ dhi,
                                                     __nv_bfloat16* __restrict__ dlo,
                                                     int K, int N) {
    __shared__ float s[32][33];
    size_t zo = (size_t)blockIdx.z * K * N;
    src += zo; dhi += zo; dlo += zo;
    int n0 = blockIdx.x * 32, k0 = blockIdx.y * 32;
    int tx = threadIdx.x & 31, ty = threadIdx.x >> 5;
#pragma unroll
    for (int i = 0; i < 4; i++)
        s[ty + 8 * i][tx] = src[(size_t)(k0 + ty + 8 * i) * N + n0 + tx];
    __syncthreads();
#pragma unroll
    for (int i = 0; i < 4; i++) {
        int n = n0 + ty + 8 * i, k = k0 + tx;
        float v = s[tx][ty + 8 * i];
        __nv_bfloat16 h, l;
        fsplit(v, h, l);
        dhi[(size_t)n * K + k] = h;
        dlo[(size_t)n * K + k] = l;
    }
}

// ---------------- embedding + positional encoding ----------------
__global__ void embed_kernel(const float* __restrict__ emb,
                             const int* __restrict__ ids,
                             float* __restrict__ x) {
    int idx = blockIdx.x * 256 + threadIdx.x;
    if (idx >= TT * DD) return;
    int t = idx >> 10;
    int d = idx & (DD - 1);
    int pos = t & (SS - 1);
    float val = emb[ids[t] * DD + d] * 32.0f;
    float ang = (float)pos * expf((float)(d & ~1) * (-9.210340371976184f / 1024.0f));
    val += (d & 1) ? cosf(ang) : sinf(ang);
    x[idx] = val;
}

// ---------------- layernorm -> split bf16 output ----------------
__global__ __launch_bounds__(256) void ln_kernel(const float* __restrict__ x,
                                                 const float* __restrict__ g,
                                                 const float* __restrict__ bta,
                                                 __nv_bfloat16* __restrict__ ohi,
                                                 __nv_bfloat16* __restrict__ olo) {
    int row = blockIdx.x;
    const float* xr = x + (size_t)row * DD;
    float s1 = 0.f, s2 = 0.f;
    for (int i = threadIdx.x; i < DD; i += 256) {
        float v = xr[i];
        s1 += v;
        s2 = fmaf(v, v, s2);
    }
    for (int o = 16; o; o >>= 1) {
        s1 += __shfl_xor_sync(0xffffffffu, s1, o);
        s2 += __shfl_xor_sync(0xffffffffu, s2, o);
    }
    __shared__ float r1[8], r2[8];
    __shared__ float smean, srstd;
    int w = threadIdx.x >> 5, lane = threadIdx.x & 31;
    if (lane == 0) { r1[w] = s1; r2[w] = s2; }
    __syncthreads();
    if (threadIdx.x == 0) {
        float t1 = 0.f, t2 = 0.f;
        for (int i = 0; i < 8; i++) { t1 += r1[i]; t2 += r2[i]; }
        float mean = t1 * (1.0f / DD);
        float var  = t2 * (1.0f / DD) - mean * mean;
        smean = mean;
        srstd = rsqrtf(var + 1e-5f);
    }
    __syncthreads();
    float mean = smean, rstd = srstd;
    for (int i = threadIdx.x; i < DD; i += 256) {
        float v = (xr[i] - mean) * rstd * g[i] + bta[i];
        __nv_bfloat16 h, l;
        fsplit(v, h, l);
        ohi[(size_t)row * DD + i] = h;
        olo[(size_t)row * DD + i] = l;
    }
}

// ---------------- split-K reduce: x += p0 + p1 + bias ----------------
__global__ __launch_bounds__(256) void addred_kernel(float* __restrict__ x,
                                                     const float* __restrict__ p0,
                                                     const float* __restrict__ p1,
                                                     const float* __restrict__ bias) {
    int idx = (blockIdx.x * 256 + threadIdx.x) * 4;
    int col = idx & (DD - 1);
    float4 a = *(const float4*)(p0 + idx);
    float4 b = *(const float4*)(p1 + idx);
    float4 c = *(const float4*)(x + idx);
    float4 bi = *(const float4*)(bias + col);
    c.x += a.x + b.x + bi.x;
    c.y += a.y + b.y + bi.y;
    c.z += a.z + b.z + bi.z;
    c.w += a.w + b.w + bi.w;
    *(float4*)(x + idx) = c;
}

// ---------------- bf16x3 mma.sync GEMM with cp.async + ldmatrix ----------------
// 128x128 tiles, 256 thr, BK=32, double-buffered cp.async, 2 CTAs/SM.
#define TST 80
#define TILE_B (128 * TST)
#define BUF_B (4 * TILE_B)
#define GEMM_SMEM (2 * BUF_B)

__device__ __forceinline__ void gemm12_body(
    const __nv_bfloat16* __restrict__ Ahg, const __nv_bfloat16* __restrict__ Alg,
    const __nv_bfloat16* __restrict__ Bhg, const __nv_bfloat16* __restrict__ Blg,
    const float* __restrict__ bias, const float* __restrict__ res,
    float* __restrict__ Cf, __nv_bfloat16* __restrict__ Chi, __nv_bfloat16* __restrict__ Clo,
    int N, int Ktot, int k0g, int klen, int act, int bm, int bn, char* smem)
{
    uint32_t sbase = smem_u32(smem);
    int t = threadIdx.x, w = t >> 5, l = t & 31;
    int wm = w >> 2, wn = w & 3;
    int m_base = wm * 64, n_base = wn * 32;

    int lrow = w * 8 + (l & 7);
    int lc = l >> 3;
    const __nv_bfloat16* gsrc[4] = {Ahg, Alg, Bhg, Blg};

    float acc[4][4][4];
#pragma unroll
    for (int mf = 0; mf < 4; mf++)
#pragma unroll
        for (int nf = 0; nf < 4; nf++)
#pragma unroll
            for (int r = 0; r < 4; r++) acc[mf][nf][r] = 0.f;

    int S = klen >> 5;

    auto load_stage = [&](int s, int bsel) {
        int k0 = k0g + (s << 5);
        uint32_t bufb = sbase + bsel * BUF_B;
#pragma unroll
        for (int tile = 0; tile < 4; tile++) {
            const __nv_bfloat16* src = gsrc[tile];
            int r0 = ((tile < 2) ? bm : bn) << 7;
            uint32_t tb = bufb + tile * TILE_B;
#pragma unroll
            for (int i = 0; i < 2; i++) {
                int row = lrow + i * 64;
                const void* gp = src + (size_t)(r0 + row) * Ktot + k0 + lc * 8;
                uint32_t dp = tb + row * TST + lc * 16;
                CP_ASYNC16(dp, gp);
            }
        }
    };

    load_stage(0, 0);
    CP_COMMIT();

    for (int s = 0; s < S; s++) {
        int b = s & 1;
        CP_WAIT0();
        __syncthreads();
        if (s + 1 < S) { load_stage(s + 1, b ^ 1); CP_COMMIT(); }

        uint32_t bufb = sbase + b * BUF_B;
        uint32_t aHb = bufb, aLb = bufb + TILE_B;
        uint32_t bHb = bufb + 2 * TILE_B, bLb = bufb + 3 * TILE_B;
#pragma unroll
        for (int ks = 0; ks < 2; ks++) {
            int cb = ks * 2;
            uint32_t bh[4][2], bl[4][2];
#pragma unroll
            for (int nfp = 0; nfp < 2; nfp++) {
                int nr = n_base + nfp * 16 + ((l >> 4) << 3) + (l & 7);
                int cc = cb + ((l >> 3) & 1);
                uint32_t addr = (uint32_t)(nr * TST + cc * 16);
                uint32_t r0, r1, r2, r3;
                LDSM4(r0, r1, r2, r3, bHb + addr);
                bh[nfp * 2][0] = r0; bh[nfp * 2][1] = r1;
                bh[nfp * 2 + 1][0] = r2; bh[nfp * 2 + 1][1] = r3;
                LDSM4(r0, r1, r2, r3, bLb + addr);
                bl[nfp * 2][0] = r0; bl[nfp * 2][1] = r1;
                bl[nfp * 2 + 1][0] = r2; bl[nfp * 2 + 1][1] = r3;
            }
#pragma unroll
            for (int mf = 0; mf < 4; mf++) {
                int mr = m_base + mf * 16 + (l & 15);
                int cc = cb + (l >> 4);
                uint32_t addr = (uint32_t)(mr * TST + cc * 16);
                uint32_t ah[4], al[4];
                LDSM4(ah[0], ah[1], ah[2], ah[3], aHb + addr);
                LDSM4(al[0], al[1], al[2], al[3], aLb + addr);
#pragma unroll
                for (int nf = 0; nf < 4; nf++) mma_bf16(acc[mf][nf], ah, bh[nf]);
#pragma unroll
                for (int nf = 0; nf < 4; nf++) mma_bf16(acc[mf][nf], ah, bl[nf]);
#pragma unroll
                for (int nf = 0; nf < 4; nf++) mma_bf16(acc[mf][nf], al, bh[nf]);
            }
        }
    }

    int gid = l >> 2, tig = l & 3;
#pragma unroll
    for (int mf = 0; mf < 4; mf++) {
        int row0 = (bm << 7) + m_base + mf * 16 + gid;
#pragma unroll
        for (int nf = 0; nf < 4; nf++) {
            int col = (bn << 7) + n_base + nf * 8 + tig * 2;
            float bx = 0.f, by = 0.f;
            if (bias) { bx = bias[col]; by = bias[col + 1]; }
#pragma unroll
            for (int half = 0; half < 2; half++) {
                int row = row0 + half * 8;
                float vx = acc[mf][nf][half * 2 + 0] + bx;
                float vy = acc[mf][nf][half * 2 + 1] + by;
                size_t o = (size_t)row * N + col;
                if (Chi) {
                    if (act) {
                        vx = 0.5f * vx * (1.0f + erff(vx * 0.70710678118654752f));
                        vy = 0.5f * vy * (1.0f + erff(vy * 0.70710678118654752f));
                    }
                    uint32_t ph, pl;
                    split_bf16x2(vx, vy, ph, pl);
                    *(uint32_t*)(Chi + o) = ph;
                    *(uint32_t*)(Clo + o) = pl;
                } else {
                    if (res) {
                        float2 rr = *(const float2*)(res + o);
                        vx += rr.x; vy += rr.y;
                    }
                    float2 ov; ov.x = vx; ov.y = vy;
                    *(float2*)(Cf + o) = ov;
                }
            }
        }
    }
}

__global__ __launch_bounds__(256, 2) void gemm12_kernel(
    const __nv_bfloat16* ah, const __nv_bfloat16* al,
    const __nv_bfloat16* bh, const __nv_bfloat16* bl,
    const float* bias, const float* res,
    float* Cf, __nv_bfloat16* Chi, __nv_bfloat16* Clo, int N, int K, int act, int swap) {
    extern __shared__ char smem[];
    int bm = swap ? blockIdx.x : blockIdx.y;
    int bn = swap ? blockIdx.y : blockIdx.x;
    gemm12_body(ah, al, bh, bl, bias, res, Cf, Chi, Clo, N, K, 0, K, act, bm, bn, smem);
}

// split-K (2-way over blockIdx.z): partial fp32 outputs, no bias/res
__global__ __launch_bounds__(256, 2) void gemm12_splitk_kernel(
    const __nv_bfloat16* ah, const __nv_bfloat16* al,
    const __nv_bfloat16* bh, const __nv_bfloat16* bl,
    float* p0, float* p1, int N, int K) {
    extern __shared__ char smem[];
    int half = blockIdx.z;
    int kh = K >> 1;
    gemm12_body(ah, al, bh, bl, nullptr, nullptr, half ? p1 : p0, nullptr, nullptr,
                N, K, half * kh, kh, 0, blockIdx.y, blockIdx.x, smem);
}

__global__ __launch_bounds__(256, 2) void gemm12_qkv_kernel(
    const __nv_bfloat16* ah, const __nv_bfloat16* al,
    const __nv_bfloat16* wqh, const __nv_bfloat16* wql,
    const __nv_bfloat16* wkh, const __nv_bfloat16* wkl,
    const __nv_bfloat16* wvh, const __nv_bfloat16* wvl,
    const float* bq, const float* bk, const float* bv,
    __nv_bfloat16* qh, __nv_bfloat16* ql,
    __nv_bfloat16* kh, __nv_bfloat16* kl,
    __nv_bfloat16* vh, __nv_bfloat16* vl) {
    extern __shared__ char smem[];
    const __nv_bfloat16 *bhp, *blp; const float* bi;
    __nv_bfloat16 *oh, *ol;
    if (blockIdx.z == 0)      { bhp = wqh; blp = wql; bi = bq; oh = qh; ol = ql; }
    else if (blockIdx.z == 1) { bhp = wkh; blp = wkl; bi = bk; oh = kh; ol = kl; }
    else                      { bhp = wvh; blp = wvl; bi = bv; oh = vh; ol = vl; }
    gemm12_body(ah, al, bhp, blp, bi, nullptr, nullptr, oh, ol, DD, DD, 0, DD, 0,
                blockIdx.y, blockIdx.x, smem);
}

// ---------------- tensor-core flash attention (bf16x3) ----------------
// CTA: 64 q rows x (h, b); 128 threads = 4 warps x m16 slice; kt tiles of 64 keys.
// Row = 64 dims x 2B = 128B; stride 144B (=4-bank step, 8-row phases conflict-free).
#define AST 144
#define ATILE (64 * AST)        // 9216 B
#define ATT_SMEM (6 * ATILE)    // Qh,Ql,Kh,Kl,Vh,Vl = 55296

__global__ __launch_bounds__(128) void flash_attn_kernel(
    const __nv_bfloat16* __restrict__ qhi, const __nv_bfloat16* __restrict__ qlo,
    const __nv_bfloat16* __restrict__ khi, const __nv_bfloat16* __restrict__ klo,
    const __nv_bfloat16* __restrict__ vhi, const __nv_bfloat16* __restrict__ vlo,
    __nv_bfloat16* __restrict__ Ohi, __nv_bfloat16* __restrict__ Olo)
{
    extern __shared__ char sm[];
    uint32_t sb = smem_u32(sm);
    uint32_t Qh = sb, Ql = sb + ATILE, Kh = sb + 2 * ATILE, Kl = sb + 3 * ATILE;
    uint32_t Vh = sb + 4 * ATILE, Vl = sb + 5 * ATILE;

    int t = threadIdx.x, wid = t >> 5, l = t & 31;
    int gid = l >> 2, tig = l & 3;
    int bqx = blockIdx.x, h = blockIdx.y, b = blockIdx.z;
    int q0 = bqx * 64;
    int m_base = wid * 16;
    size_t tok0 = (size_t)(b * SS) * DD + h * 64;   // +token*DD to index

    // ---- load Q tile (hi/lo) ----
    {
        int chunk = t & 7, row0 = t >> 3;           // 16 rows per pass
#pragma unroll
        for (int i = 0; i < 4; i++) {
            int row = row0 + 16 * i;
            size_t g = tok0 + (size_t)(q0 + row) * DD + chunk * 8;
            CP_ASYNC16(Qh + row * AST + chunk * 16, qhi + g);
            CP_ASYNC16(Ql + row * AST + chunk * 16, qlo + g);
        }
    }
    CP_COMMIT();

    float o[8][4];
#pragma unroll
    for (int nf = 0; nf < 8; nf++)
#pragma unroll
        for (int r = 0; r < 4; r++) o[nf][r] = 0.f;
    float m0 = -1e30f, m1 = -1e30f, l0 = 0.f, l1 = 0.f;

    int ntiles = bqx + 1;
    for (int kt = 0; kt < ntiles; kt++) {
        // ---- load K/V tile (hi/lo) ----
        {
            int chunk = t & 7, row0 = t >> 3;
#pragma unroll
            for (int i = 0; i < 4; i++) {
                int row = row0 + 16 * i;
                size_t g = tok0 + (size_t)(kt * 64 + row) * DD + chunk * 8;
                CP_ASYNC16(Kh + row * AST + chunk * 16, khi + g);
                CP_ASYNC16(Kl + row * AST + chunk * 16, klo + g);
                CP_ASYNC16(Vh + row * AST + chunk * 16, vhi + g);
                CP_ASYNC16(Vl + row * AST + chunk * 16, vlo + g);
            }
        }
        CP_COMMIT();
        CP_WAIT0();
        __syncthreads();

        // ---- S = Q K^T (3-pass bf16x3) ----
        float sacc[8][4];
#pragma unroll
        for (int nf = 0; nf < 8; nf++)
#pragma unroll
            for (int r = 0; r < 4; r++) sacc[nf][r] = 0.f;
#pragma unroll
        for (int kb = 0; kb < 4; kb++) {
            uint32_t aoff = (uint32_t)((m_base + (l & 15)) * AST + (kb * 2 + (l >> 4)) * 16);
            uint32_t qh4[4], ql4[4];
            LDSM4(qh4[0], qh4[1], qh4[2], qh4[3], Qh + aoff);
            LDSM4(ql4[0], ql4[1], ql4[2], ql4[3], Ql + aoff);
#pragma unroll
            for (int ng = 0; ng < 4; ng++) {
                uint32_t boff = (uint32_t)((ng * 16 + ((l >> 4) << 3) + (l & 7)) * AST
                                           + (kb * 2 + ((l >> 3) & 1)) * 16);
                uint32_t kh4[4], kl4[4];
                LDSM4(kh4[0], kh4[1], kh4[2], kh4[3], Kh + boff);
                LDSM4(kl4[0], kl4[1], kl4[2], kl4[3], Kl + boff);
                mma_bf16(sacc[2 * ng],     qh4, kh4);
                mma_bf16(sacc[2 * ng + 1], qh4, kh4 + 2);
                mma_bf16(sacc[2 * ng],     qh4, kl4);
                mma_bf16(sacc[2 * ng + 1], qh4, kl4 + 2);
                mma_bf16(sacc[2 * ng],     ql4, kh4);
                mma_bf16(sacc[2 * ng + 1], ql4, kh4 + 2);
            }
        }

        // ---- scale + causal mask ----
#pragma unroll
        for (int nf = 0; nf < 8; nf++)
#pragma unroll
            for (int r = 0; r < 4; r++) sacc[nf][r] *= 0.125f;
        if (kt == bqx) {
            int grow0 = q0 + m_base + gid, grow1 = grow0 + 8;
#pragma unroll
            for (int nf = 0; nf < 8; nf++) {
                int gc = kt * 64 + nf * 8 + tig * 2;
                if (gc > grow0)     sacc[nf][0] = -1e30f;
                if (gc + 1 > grow0) sacc[nf][1] = -1e30f;
                if (gc > grow1)     sacc[nf][2] = -1e30f;
                if (gc + 1 > grow1) sacc[nf][3] = -1e30f;
            }
        }

        // ---- online softmax (registers + shfl over 4 lanes/row) ----
        float mx0 = -1e30f, mx1 = -1e30f;
#pragma unroll
        for (int nf = 0; nf < 8; nf++) {
            mx0 = fmaxf(mx0, fmaxf(sacc[nf][0], sacc[nf][1]));
            mx1 = fmaxf(mx1, fmaxf(sacc[nf][2], sacc[nf][3]));
        }
        mx0 = fmaxf(mx0, __shfl_xor_sync(0xffffffffu, mx0, 1));
        mx0 = fmaxf(mx0, __shfl_xor_sync(0xffffffffu, mx0, 2));
        mx1 = fmaxf(mx1, __shfl_xor_sync(0xffffffffu, mx1, 1));
        mx1 = fmaxf(mx1, __shfl_xor_sync(0xffffffffu, mx1, 2));
        float mn0 = fmaxf(m0, mx0), mn1 = fmaxf(m1, mx1);
        float f0 = __expf(m0 - mn0), f1 = __expf(m1 - mn1);
        float s0 = 0.f, s1 = 0.f;
#pragma unroll
        for (int nf = 0; nf < 8; nf++) {
            float p0 = __expf(sacc[nf][0] - mn0);
            float p1 = __expf(sacc[nf][1] - mn0);
            float p2 = __expf(sacc[nf][2] - mn1);
            float p3 = __expf(sacc[nf][3] - mn1);
            sacc[nf][0] = p0; sacc[nf][1] = p1; sacc[nf][2] = p2; sacc[nf][3] = p3;
            s0 += p0 + p1; s1 += p2 + p3;
        }
        s0 += __shfl_xor_sync(0xffffffffu, s0, 1);
        s0 += __shfl_xor_sync(0xffffffffu, s0, 2);
        s1 += __shfl_xor_sync(0xffffffffu, s1, 1);
        s1 += __shfl_xor_sync(0xffffffffu, s1, 2);
        l0 = l0 * f0 + s0; l1 = l1 * f1 + s1;
        m0 = mn0; m1 = mn1;
#pragma unroll
        for (int nf = 0; nf < 8; nf++) {
            o[nf][0] *= f0; o[nf][1] *= f0; o[nf][2] *= f1; o[nf][3] *= f1;
        }

        // ---- P -> A fragments (C(m16n16) == A(m16k16) identity), split hi/lo ----
        uint32_t phi[4][4], plo[4][4];
#pragma unroll
        for (int kb = 0; kb < 4; kb++) {
            split_bf16x2(sacc[2 * kb][0],     sacc[2 * kb][1],     phi[kb][0], plo[kb][0]);
            split_bf16x2(sacc[2 * kb][2],     sacc[2 * kb][3],     phi[kb][1], plo[kb][1]);
            split_bf16x2(sacc[2 * kb + 1][0], sacc[2 * kb + 1][1], phi[kb][2], plo[kb][2]);
            split_bf16x2(sacc[2 * kb + 1][2], sacc[2 * kb + 1][3], phi[kb][3], plo[kb][3]);
        }

        // ---- O += P V (V via ldmatrix.trans, 3-pass) ----
#pragma unroll
        for (int kb = 0; kb < 4; kb++) {
#pragma unroll
            for (int dg = 0; dg < 4; dg++) {
                uint32_t voff = (uint32_t)((kb * 16 + ((l >> 3) & 1) * 8 + (l & 7)) * AST
                                           + dg * 32 + (l >> 4) * 16);
                uint32_t vh4[4], vl4[4];
                LDSM4T(vh4[0], vh4[1], vh4[2], vh4[3], Vh + voff);
                LDSM4T(vl4[0], vl4[1], vl4[2], vl4[3], Vl + voff);
                mma_bf16(o[2 * dg],     phi[kb], vh4);
                mma_bf16(o[2 * dg + 1], phi[kb], vh4 + 2);
                mma_bf16(o[2 * dg],     phi[kb], vl4);
                mma_bf16(o[2 * dg + 1], phi[kb], vl4 + 2);
                mma_bf16(o[2 * dg],     plo[kb], vh4);
                mma_bf16(o[2 * dg + 1], plo[kb], vh4 + 2);
            }
        }
        __syncthreads();
    }

    // ---- normalize + split-store ----
    float inv0 = 1.0f / l0, inv1 = 1.0f / l1;
    int row0 = b * SS + q0 + m_base + gid;
#pragma unroll
    for (int nf = 0; nf < 8; nf++) {
        int col = h * 64 + nf * 8 + tig * 2;
        uint32_t ph, pl;
        split_bf16x2(o[nf][0] * inv0, o[nf][1] * inv0, ph, pl);
        size_t oa = (size_t)row0 * DD + col;
        *(uint32_t*)(Ohi + oa) = ph;
        *(uint32_t*)(Olo + oa) = pl;
        split_bf16x2(o[nf][2] * inv1, o[nf][3] * inv1, ph, pl);
        size_t ob = (size_t)(row0 + 8) * DD + col;
        *(uint32_t*)(Ohi + ob) = ph;
        *(uint32_t*)(Olo + ob) = pl;
    }
}

// ---------------- launch ----------------
extern "C" void kernel_launch(void* const* d_in, const int* in_sizes, int n_in,
                              void* d_out, int out_size) {
    const float* emb  = (const float*)d_in[0];
    const float* Wq   = (const float*)d_in[1];
    const float* bq   = (const float*)d_in[2];
    const float* Wk   = (const float*)d_in[3];
    const float* bk   = (const float*)d_in[4];
    const float* Wv   = (const float*)d_in[5];
    const float* bv   = (const float*)d_in[6];
    const float* Wo   = (const float*)d_in[7];
    const float* bo   = (const float*)d_in[8];
    const float* ln1g = (const float*)d_in[9];
    const float* ln1b = (const float*)d_in[10];
    const float* W1   = (const float*)d_in[11];
    const float* b1   = (const float*)d_in[12];
    const float* W2   = (const float*)d_in[13];
    const float* b2   = (const float*)d_in[14];
    const float* ln2g = (const float*)d_in[15];
    const float* ln2b = (const float*)d_in[16];
    const float* lnfg = (const float*)d_in[17];
    const float* lnfb = (const float*)d_in[18];
    const float* Wout = (const float*)d_in[19];
    const int*   ids  = (const int*)d_in[20];

    __nv_bfloat16 *whi, *wlo, *hhi, *hlo, *athi, *atlo, *ffhi, *fflo;
    __nv_bfloat16 *qhi, *qlo, *khi, *klo, *vhi, *vlo;
    float *x, *p0, *p1;
    cudaGetSymbolAddress((void**)&whi, g_whi);
    cudaGetSymbolAddress((void**)&wlo, g_wlo);
    cudaGetSymbolAddress((void**)&x,   g_x);
    cudaGetSymbolAddress((void**)&p0,  g_p0);
    cudaGetSymbolAddress((void**)&p1,  g_p1);
    cudaGetSymbolAddress((void**)&qhi, g_qhi);
    cudaGetSymbolAddress((void**)&qlo, g_qlo);
    cudaGetSymbolAddress((void**)&khi, g_khi);
    cudaGetSymbolAddress((void**)&klo, g_klo);
    cudaGetSymbolAddress((void**)&vhi, g_vhi);
    cudaGetSymbolAddress((void**)&vlo, g_vlo);
    cudaGetSymbolAddress((void**)&hhi, g_hhi);
    cudaGetSymbolAddress((void**)&hlo, g_hlo);
    cudaGetSymbolAddress((void**)&athi, g_athi);
    cudaGetSymbolAddress((void**)&atlo, g_atlo);
    cudaGetSymbolAddress((void**)&ffhi, g_ffhi);
    cudaGetSymbolAddress((void**)&fflo, g_fflo);

    static int attr_set = 0;
    if (!attr_set) {
        cudaFuncSetAttribute(flash_attn_kernel, cudaFuncAttributeMaxDynamicSharedMemorySize, ATT_SMEM);
        cudaFuncSetAttribute(gemm12_kernel, cudaFuncAttributeMaxDynamicSharedMemorySize, GEMM_SMEM);
        cudaFuncSetAttribute(gemm12_splitk_kernel, cudaFuncAttributeMaxDynamicSharedMemorySize, GEMM_SMEM);
        cudaFuncSetAttribute(gemm12_qkv_kernel, cudaFuncAttributeMaxDynamicSharedMemorySize, GEMM_SMEM);
        attr_set = 1;
    }

    // ---- weight prep: transpose + split ----
    tsplit_kernel<<<dim3(DD / 32, DD / 32, LL), 256>>>(Wq, whi + OFF_WQ, wlo + OFF_WQ, DD, DD);
    tsplit_kernel<<<dim3(DD / 32, DD / 32, LL), 256>>>(Wk, whi + OFF_WK, wlo + OFF_WK, DD, DD);
    tsplit_kernel<<<dim3(DD / 32, DD / 32, LL), 256>>>(Wv, whi + OFF_WV, wlo + OFF_WV, DD, DD);
    tsplit_kernel<<<dim3(DD / 32, DD / 32, LL), 256>>>(Wo, whi + OFF_WO, wlo + OFF_WO, DD, DD);
    tsplit_kernel<<<dim3(FFD / 32, DD / 32, LL), 256>>>(W1, whi + OFF_W1, wlo + OFF_W1, DD, FFD);
    tsplit_kernel<<<dim3(DD / 32, FFD / 32, LL), 256>>>(W2, whi + OFF_W2, wlo + OFF_W2, FFD, DD);
    tsplit_kernel<<<dim3(VV / 32, DD / 32, 1), 256>>>(Wout, whi + OFF_WOUT, wlo + OFF_WOUT, DD, VV);

    embed_kernel<<<(TT * DD) / 256, 256>>>(emb, ids, x);

    dim3 gSK(DD / 128, TT / 128, 2);     // (8, 16, 2) = 256 CTAs (split-K)
    dim3 gQKV(DD / 128, TT / 128, 3);    // (8, 16, 3)
    dim3 gFF1(FFD / 128, TT / 128);      // (32, 16)
    dim3 gOut(TT / 128, VV / 128);       // (16, 250)
    dim3 gAttn(SS / 64, HH, BB);         // (16, 16, 2)
    int gRed = (TT * DD) / (256 * 4);    // 2048 blocks

    for (int l = 0; l < LL; l++) {
        size_t wo1 = (size_t)l * DD * DD;
        size_t woF = (size_t)l * DD * FFD;
        ln_kernel<<<TT, 256>>>(x, ln1g + l * DD, ln1b + l * DD, hhi, hlo);
        gemm12_qkv_kernel<<<gQKV, 256, GEMM_SMEM>>>(
            hhi, hlo,
            whi + OFF_WQ + wo1, wlo + OFF_WQ + wo1,
            whi + OFF_WK + wo1, wlo + OFF_WK + wo1,
            whi + OFF_WV + wo1, wlo + OFF_WV + wo1,
            bq + l * DD, bk + l * DD, bv + l * DD,
            qhi, qlo, khi, klo, vhi, vlo);
        flash_attn_kernel<<<gAttn, 128, ATT_SMEM>>>(qhi, qlo, khi, klo, vhi, vlo, athi, atlo);
        // x += attn @ Wo + bo  (split-K over 2 halves, then reduce)
        gemm12_splitk_kernel<<<gSK, 256, GEMM_SMEM>>>(
            athi, atlo, whi + OFF_WO + wo1, wlo + OFF_WO + wo1, p0, p1, DD, DD);
        addred_kernel<<<gRed, 256>>>(x, p0, p1, bo + l * DD);
        ln_kernel<<<TT, 256>>>(x, ln2g + l * DD, ln2b + l * DD, hhi, hlo);
        gemm12_kernel<<<gFF1, 256, GEMM_SMEM>>>(
            hhi, hlo, whi + OFF_W1 + woF, wlo + OFF_W1 + woF,
            b1 + l * FFD, nullptr, nullptr, ffhi, fflo, FFD, DD, 1, 0);
        // x += ff @ W2 + b2  (split-K)
        gemm12_splitk_kernel<<<gSK, 256, GEMM_SMEM>>>(
            ffhi, fflo, whi + OFF_W2 + woF, wlo + OFF_W2 + woF, p0, p1, DD, FFD);
        addred_kernel<<<gRed, 256>>>(x, p0, p1, b2 + l * DD);
    }
    ln_kernel<<<TT, 256>>>(x, lnfg, lnfb, hhi, hlo);
    gemm12_kernel<<<gOut, 256, GEMM_SMEM>>>(
        hhi, hlo, whi + OFF_WOUT, wlo + OFF_WOUT,
        nullptr, nullptr, (float*)d_out, nullptr, nullptr, VV, DD, 0, 1);
}